// round 10
// baseline (speedup 1.0000x reference)
#include <cuda_runtime.h>
#include <cuda_fp16.h>
#include <stdint.h>

#define B_ 16
#define S_ 2048
#define H_ 1024
#define M_TOTAL (B_ * S_)   // 32768

#define BM 128
#define BN 128
#define BK 64
#define K_ITERS (H_ / BK)   // 16
#define NSTAGES 3
#define N_TILES 8                         // H_/BN
#define TOTAL_TILES ((M_TOTAL / BM) * N_TILES)  // 2048
#define GRID_P 296                        // 148 SMs x 2 CTAs

// Tile rows are 64 halves = 128B = 8 chunks of 16B, XOR-swizzled (c ^ (row&7))
#define A_BYTES (BM * 128)               // 16384
#define STAGE_BYTES (2 * A_BYTES)        // 32768
#define SMEM_TOTAL (NSTAGES * STAGE_BYTES + 1024)  // 99328

// Device scratch (static arrays only — no allocs allowed)
__device__ float g_hidb[B_ * H_];
__device__ float g_logits[M_TOTAL];
__device__ __align__(16) __half g_ench[(size_t)M_TOTAL * H_];  // enc fp16 (64MB)
__device__ __align__(16) __half g_w2th[(size_t)H_ * H_];       // W2^T fp16 [n][k]

// ---------------------------------------------------------------------------
#define CP_ASYNC16(dst, src) \
    asm volatile("cp.async.cg.shared.global [%0], [%1], 16;" :: "r"(dst), "l"(src))
#define CP_COMMIT() asm volatile("cp.async.commit_group;" ::: "memory")

__device__ __forceinline__ uint32_t smem_u32(const void* p) {
    uint32_t a;
    asm("{ .reg .u64 t; cvta.to.shared.u64 t, %1; cvt.u32.u64 %0, t; }" : "=r"(a) : "l"(p));
    return a;
}

// memory clobber (not volatile): ordered against barriers/stores, but the
// scheduler may still reorder among independent LDSM/HMMA.
__device__ __forceinline__ void ldmx4(uint32_t* r, uint32_t addr) {
    asm("ldmatrix.sync.aligned.m8n8.x4.shared.b16 {%0,%1,%2,%3}, [%4];"
        : "=r"(r[0]), "=r"(r[1]), "=r"(r[2]), "=r"(r[3]) : "r"(addr) : "memory");
}

__device__ __forceinline__ void mma_f16(float* d, const uint32_t* a, const uint32_t* b) {
    asm("mma.sync.aligned.m16n8k16.row.col.f32.f16.f16.f32 "
        "{%0,%1,%2,%3}, {%4,%5,%6,%7}, {%8,%9}, {%0,%1,%2,%3};\n"
        : "+f"(d[0]), "+f"(d[1]), "+f"(d[2]), "+f"(d[3])
        : "r"(a[0]), "r"(a[1]), "r"(a[2]), "r"(a[3]), "r"(b[0]), "r"(b[1]));
}

// Eigen/XLA rational tanh, FMA-pipe only. |err| ~ 1e-7 on [-8, 8].
__device__ __forceinline__ float fast_tanh(float x) {
    x = fminf(fmaxf(x, -7.99881172f), 7.99881172f);
    float x2 = x * x;
    float p = -2.76076847742355e-16f;
    p = fmaf(p, x2, 2.00018790482477e-13f);
    p = fmaf(p, x2, -8.60467152213735e-11f);
    p = fmaf(p, x2, 5.12229709037114e-08f);
    p = fmaf(p, x2, 1.48572235717979e-05f);
    p = fmaf(p, x2, 6.37261928875436e-04f);
    p = fmaf(p, x2, 4.89352455891786e-03f);
    p = p * x;
    float q = 1.19825839466702e-06f;
    q = fmaf(q, x2, 1.18534705686654e-04f);
    q = fmaf(q, x2, 2.26843463243900e-03f);
    q = fmaf(q, x2, 4.89352518554385e-03f);
    float r = __uint_as_float(0x7EF127EAu - __float_as_uint(q));
    r = r * (2.0f - q * r);
    r = r * (2.0f - q * r);
    r = r * (2.0f - q * r);
    return p * r;
}

// ---------------------------------------------------------------------------
// Kernel 0a: convert enc fp32 -> fp16 (8 elements per thread)
__global__ __launch_bounds__(256) void conv_enc_kernel(const float* __restrict__ enc) {
    size_t i = ((size_t)blockIdx.x * 256 + threadIdx.x) * 8;
    float4 v0 = *reinterpret_cast<const float4*>(enc + i);
    float4 v1 = *reinterpret_cast<const float4*>(enc + i + 4);
    __half2 h0 = __floats2half2_rn(v0.x, v0.y);
    __half2 h1 = __floats2half2_rn(v0.z, v0.w);
    __half2 h2 = __floats2half2_rn(v1.x, v1.y);
    __half2 h3 = __floats2half2_rn(v1.z, v1.w);
    uint4 u;
    u.x = *reinterpret_cast<uint32_t*>(&h0);
    u.y = *reinterpret_cast<uint32_t*>(&h1);
    u.z = *reinterpret_cast<uint32_t*>(&h2);
    u.w = *reinterpret_cast<uint32_t*>(&h3);
    *reinterpret_cast<uint4*>(&g_ench[i]) = u;
}

// ---------------------------------------------------------------------------
// Kernel 0b: transpose W2 -> g_w2th[n][k] fp16, + zero logits/hidb scratch
__global__ __launch_bounds__(256) void conv_w2t_kernel(const float* __restrict__ W_attn) {
    __shared__ float tile[32][33];
    int bx = blockIdx.x, by = blockIdx.y;
    int tx = threadIdx.x, ty = threadIdx.y;
    int n = bx * 32 + tx;
    #pragma unroll
    for (int j = 0; j < 32; j += 8)
        tile[ty + j][tx] = W_attn[(size_t)(H_ + by * 32 + ty + j) * H_ + n];
    __syncthreads();
    int k = by * 32 + tx;
    #pragma unroll
    for (int j = 0; j < 32; j += 8)
        g_w2th[(size_t)(bx * 32 + ty + j) * H_ + k] = __float2half_rn(tile[tx][ty + j]);

    int bid = by * 32 + bx;
    int t = ty * 32 + tx;
    if (bid < 64) {
        g_logits[bid * 512 + t] = 0.0f;
        g_logits[bid * 512 + t + 256] = 0.0f;
    } else if (bid < 128) {
        g_hidb[(bid - 64) * 256 + t] = 0.0f;
    }
}

// ---------------------------------------------------------------------------
// Kernel 1: g_hidb[b][n] += partial(hidden @ W1) + bias (k-split, W1 read once)
__global__ __launch_bounds__(256) void prep_kernel(
    const float* __restrict__ hidden,
    const float* __restrict__ W_attn,
    const float* __restrict__ b_attn)
{
    __shared__ float sh[16][64];
    int n = blockIdx.x * 256 + threadIdx.x;
    int k0 = blockIdx.y * 64;
    for (int i = threadIdx.x; i < 16 * 64; i += 256)
        sh[i >> 6][i & 63] = hidden[(i >> 6) * H_ + k0 + (i & 63)];
    __syncthreads();

    float acc[16];
    float bias = (blockIdx.y == 0) ? b_attn[n] : 0.0f;
    #pragma unroll
    for (int b = 0; b < 16; ++b) acc[b] = bias;

    #pragma unroll 8
    for (int k = 0; k < 64; ++k) {
        float w = W_attn[(size_t)(k0 + k) * H_ + n];
        #pragma unroll
        for (int b = 0; b < 16; ++b) acc[b] = fmaf(sh[b][k], w, acc[b]);
    }
    #pragma unroll
    for (int b = 0; b < 16; ++b) atomicAdd(&g_hidb[b * H_ + n], acc[b]);
}

// ---------------------------------------------------------------------------
// Kernel 2: persistent fp16 mma GEMM. 296 CTAs, each owns tiles bid, bid+296,...
// The 3-stage cp.async ring never drains across tile boundaries: a load cursor
// (lt, li, lstage) runs 2 iters ahead of the compute cursor.
__global__ __launch_bounds__(256, 2) void attn_gemm_kernel(
    const float* __restrict__ v)
{
    extern __shared__ char smem[];
    float* sh_hb = (float*)(smem + NSTAGES * STAGE_BYTES);
    float* sh_v  = sh_hb + BN;
    const uint32_t smem_base = smem_u32(smem);

    const int tid = threadIdx.x;
    const int lane = tid & 31;
    const int warp = tid >> 5;
    const int wm = warp >> 2;       // 0..1 (64-row slab)
    const int wn = warp & 3;        // 0..3 (32-col slab)
    const int r = lane >> 2;        // 0..7
    const int c = lane & 3;         // 0..3
    const int i8 = lane & 7;
    const int sub = lane >> 3;      // 0..3 (ldmatrix octet)

    // --- cp.async addressing (fixed per thread) ---
    const int r0 = tid >> 3;
    const int cc = tid & 7;
    const uint32_t st_off = (uint32_t)r0 * 128u + (uint32_t)((cc ^ (r0 & 7)) << 4);

    // --- ldmatrix addressing (fixed per thread) ---
    const uint32_t a_row  = (uint32_t)(wm * 64 + i8 + 8 * (sub & 1));
    const uint32_t a_csub = (uint32_t)(sub >> 1);
    const uint32_t a_x    = a_row & 7;
    const uint32_t a_base = a_row * 128u;
    const uint32_t b_row  = (uint32_t)(wn * 32 + i8 + 8 * (sub >> 1));
    const uint32_t b_csub = (uint32_t)(sub & 1);
    const uint32_t b_x    = b_row & 7;
    const uint32_t b_base = A_BYTES + b_row * 128u;

    // --- load cursor ---
    int lt = blockIdx.x;            // tile being loaded
    int li = 0;                     // k-iter within lt
    int lstage = 0;                 // stage for next load
    const __half* a_gl = &g_ench[(size_t)(((lt >> 3) * BM) + r0) * H_ + cc * 8];
    const __half* b_gl = &g_w2th[(size_t)(((lt & 7) * BN) + r0) * H_ + cc * 8];

    // prologue: fill 2 stages (iters 0,1 of first tile)
    #pragma unroll
    for (int s = 0; s < 2; ++s) {
        uint32_t sb = smem_base + lstage * STAGE_BYTES;
        #pragma unroll
        for (int p = 0; p < 4; ++p) {
            CP_ASYNC16(sb + st_off + p * 4096u, a_gl + (size_t)p * 32 * H_);
            CP_ASYNC16(sb + A_BYTES + st_off + p * 4096u, b_gl + (size_t)p * 32 * H_);
        }
        CP_COMMIT();
        ++li; a_gl += BK; b_gl += BK;
        lstage = (lstage + 1 == NSTAGES) ? 0 : lstage + 1;
    }

    float acc[2][4][4];
    float acc2[2][4][4];
    #pragma unroll
    for (int mm = 0; mm < 2; ++mm)
        #pragma unroll
        for (int nn = 0; nn < 4; ++nn)
            #pragma unroll
            for (int i = 0; i < 4; ++i) { acc[mm][nn][i] = 0.0f; acc2[mm][nn][i] = 0.0f; }

    int cstage = 0;                 // compute stage

    for (int ct = blockIdx.x; ct < TOTAL_TILES; ct += GRID_P) {
        const int m0 = (ct >> 3) * BM;
        const int n0 = (ct & 7) * BN;
        const int batch = m0 >> 11;
        const bool last_tile = (ct + GRID_P >= TOTAL_TILES);

        for (int i = 0; i < K_ITERS; ++i) {
            if (last_tile && i == K_ITERS - 1)
                asm volatile("cp.async.wait_group 0;" ::: "memory");
            else
                asm volatile("cp.async.wait_group 1;" ::: "memory");
            __syncthreads();

            if (i == 0 && tid < BN) {
                sh_hb[tid] = g_hidb[batch * H_ + n0 + tid];
                sh_v[tid]  = v[n0 + tid];
            }

            const uint32_t sa = smem_base + cstage * STAGE_BYTES;
            cstage = (cstage + 1 == NSTAGES) ? 0 : cstage + 1;
            const bool refill = (lt < TOTAL_TILES);
            const uint32_t sbb = smem_base + lstage * STAGE_BYTES;

            #pragma unroll
            for (int ks = 0; ks < 4; ++ks) {
                // B fragments first (needed by every mma of this ks)
                uint32_t bf[4][2];
                {
                    uint32_t tmp[4];
                    #pragma unroll
                    for (int nnp = 0; nnp < 2; ++nnp) {
                        uint32_t addr = sa + b_base + nnp * (16u * 128u)
                                      + (((2 * ks + b_csub) ^ b_x) << 4);
                        ldmx4(tmp, addr);
                        bf[nnp * 2 + 0][0] = tmp[0];
                        bf[nnp * 2 + 0][1] = tmp[1];
                        bf[nnp * 2 + 1][0] = tmp[2];
                        bf[nnp * 2 + 1][1] = tmp[3];
                    }
                }
                // Interleave A fragment loads with mma groups
                uint32_t af[4][4];
                {
                    uint32_t addr0 = sa + a_base + (((2 * ks + a_csub) ^ a_x) << 4);
                    ldmx4(af[0], addr0);
                    #pragma unroll
                    for (int mm = 0; mm < 4; ++mm) {
                        if (mm < 3)
                            ldmx4(af[mm + 1], addr0 + (uint32_t)(mm + 1) * (16u * 128u));
                        float (*ac)[4] = (mm < 2) ? acc[mm] : acc2[mm - 2];
                        #pragma unroll
                        for (int nn = 0; nn < 4; ++nn)
                            mma_f16(ac[nn], af[mm], bf[nn]);
                    }
                }
                // Deferred refill in the HMMA shadow: A after ks0, B after ks1
                if (ks == 0 && refill) {
                    #pragma unroll
                    for (int p = 0; p < 4; ++p)
                        CP_ASYNC16(sbb + st_off + p * 4096u, a_gl + (size_t)p * 32 * H_);
                }
                if (ks == 1 && refill) {
                    #pragma unroll
                    for (int p = 0; p < 4; ++p)
                        CP_ASYNC16(sbb + A_BYTES + st_off + p * 4096u, b_gl + (size_t)p * 32 * H_);
                    CP_COMMIT();
                    // advance load cursor
                    lstage = (lstage + 1 == NSTAGES) ? 0 : lstage + 1;
                    if (++li == K_ITERS) {
                        li = 0;
                        lt += GRID_P;
                        if (lt < TOTAL_TILES) {
                            a_gl = &g_ench[(size_t)(((lt >> 3) * BM) + r0) * H_ + cc * 8];
                            b_gl = &g_w2th[(size_t)(((lt & 7) * BN) + r0) * H_ + cc * 8];
                        }
                    } else {
                        a_gl += BK; b_gl += BK;
                    }
                }
            }
        }

        // Epilogue for tile ct: tanh(acc + hidb) * v, lane-reduce, atomicAdd.
        // Safe vs next tile: sh_hb writes happen after the next iter's barrier.
        float hcol[8], vcol[8];
        #pragma unroll
        for (int nn = 0; nn < 4; ++nn)
            #pragma unroll
            for (int bit = 0; bit < 2; ++bit) {
                int col = wn * 32 + nn * 8 + c * 2 + bit;
                hcol[nn * 2 + bit] = sh_hb[col];
                vcol[nn * 2 + bit] = sh_v[col];
            }

        #pragma unroll
        for (int mm = 0; mm < 4; ++mm) {
            float (*ac)[4] = (mm < 2) ? acc[mm] : acc2[mm - 2];
            float p0 = 0.0f, p1 = 0.0f;
            #pragma unroll
            for (int nn = 0; nn < 4; ++nn) {
                p0 += fast_tanh(ac[nn][0] + hcol[nn * 2 + 0]) * vcol[nn * 2 + 0];
                p0 += fast_tanh(ac[nn][1] + hcol[nn * 2 + 1]) * vcol[nn * 2 + 1];
                p1 += fast_tanh(ac[nn][2] + hcol[nn * 2 + 0]) * vcol[nn * 2 + 0];
                p1 += fast_tanh(ac[nn][3] + hcol[nn * 2 + 1]) * vcol[nn * 2 + 1];
            }
            p0 += __shfl_xor_sync(0xffffffffu, p0, 1);
            p0 += __shfl_xor_sync(0xffffffffu, p0, 2);
            p1 += __shfl_xor_sync(0xffffffffu, p1, 1);
            p1 += __shfl_xor_sync(0xffffffffu, p1, 2);
            if (c == 0) {
                int rbase = m0 + wm * 64 + mm * 16 + r;
                atomicAdd(&g_logits[rbase], p0);
                atomicAdd(&g_logits[rbase + 8], p1);
            }
        }
        // reset accumulators for the next tile
        #pragma unroll
        for (int mm = 0; mm < 2; ++mm)
            #pragma unroll
            for (int nn = 0; nn < 4; ++nn)
                #pragma unroll
                for (int q = 0; q < 4; ++q) { acc[mm][nn][q] = 0.0f; acc2[mm][nn][q] = 0.0f; }
    }
}

// ---------------------------------------------------------------------------
// Kernel 3: softmax over S per batch row
__global__ __launch_bounds__(256) void softmax_kernel(float* __restrict__ out) {
    __shared__ float red[256];
    int b = blockIdx.x;
    int t = threadIdx.x;
    const float* lg = g_logits + b * S_;

    float m = -1e30f;
    for (int i = t; i < S_; i += 256) m = fmaxf(m, lg[i]);
    red[t] = m;
    __syncthreads();
    for (int s = 128; s > 0; s >>= 1) {
        if (t < s) red[t] = fmaxf(red[t], red[t + s]);
        __syncthreads();
    }
    m = red[0];
    __syncthreads();

    float sum = 0.0f;
    for (int i = t; i < S_; i += 256) sum += expf(lg[i] - m);
    red[t] = sum;
    __syncthreads();
    for (int s = 128; s > 0; s >>= 1) {
        if (t < s) red[t] += red[t + s];
        __syncthreads();
    }
    float inv = 1.0f / red[0];

    for (int i = t; i < S_; i += 256) out[b * S_ + i] = expf(lg[i] - m) * inv;
}

// ---------------------------------------------------------------------------
extern "C" void kernel_launch(void* const* d_in, const int* in_sizes, int n_in,
                              void* d_out, int out_size) {
    const float* hidden  = (const float*)d_in[0];   // (16, 1024)
    const float* enc     = (const float*)d_in[1];   // (16, 2048, 1024)
    const float* W_attn  = (const float*)d_in[2];   // (2048, 1024)
    const float* b_attn  = (const float*)d_in[3];   // (1024,)
    const float* v       = (const float*)d_in[4];   // (1024,)
    float* out = (float*)d_out;                     // (16, 2048)

    cudaFuncSetAttribute(attn_gemm_kernel,
                         cudaFuncAttributeMaxDynamicSharedMemorySize, SMEM_TOTAL);

    conv_enc_kernel<<<(size_t)M_TOTAL * H_ / 8 / 256, 256>>>(enc);
    conv_w2t_kernel<<<dim3(32, 32), dim3(32, 8)>>>(W_attn);
    prep_kernel<<<dim3(4, 16), 256>>>(hidden, W_attn, b_attn);
    attn_gemm_kernel<<<GRID_P, 256, SMEM_TOTAL>>>(v);
    softmax_kernel<<<B_, 256>>>(out);
}